// round 12
// baseline (speedup 1.0000x reference)
#include <cuda_runtime.h>
#include <cuda_fp16.h>
#include <cstdint>

// ======================= problem constants =======================
static constexpr int MDIM = 16384;   // 8*2048
static constexpr int NDIM = 4096;
static constexpr int KDIM = 4096;

static constexpr int BM = 128;
static constexpr int BN = 128;
static constexpr int BK = 64;            // 64 fp16 = 128B per row
static constexpr int NSTAGE = 3;
static constexpr int NIT = KDIM / BK;    // 64

static constexpr int A_BYTES = BM * BK * 2;            // 16384
static constexpr int B_BYTES = BN * BK * 2;            // 16384
static constexpr int STAGE_BYTES = A_BYTES + B_BYTES;  // 32768

static constexpr uint32_t SM_BIAS   = 0;     // 128 floats
static constexpr uint32_t SM_STAGE0 = 1024;
static constexpr uint32_t SMEM_TOTAL = SM_STAGE0 + NSTAGE * STAGE_BYTES; // 99328

// ======================= scratch (static device globals) =========
__device__ __align__(256) __half g_xh[(size_t)MDIM * KDIM];  // 128 MB
__device__ __align__(256) __half g_wb[(size_t)NDIM * KDIM];  //  32 MB

// ======================= helpers =================================
__device__ __forceinline__ uint32_t smem_u32(const void* p) {
    uint32_t a;
    asm("{ .reg .u64 t; cvta.to.shared.u64 t, %1; cvt.u32.u64 %0, t; }"
        : "=r"(a) : "l"(p));
    return a;
}

__device__ __forceinline__ void cpasync16(uint32_t saddr, const void* g) {
    asm volatile("cp.async.cg.shared.global [%0], [%1], 16;" :: "r"(saddr), "l"(g));
}

__device__ __forceinline__ void ldsm_x4(uint32_t& r0, uint32_t& r1,
                                        uint32_t& r2, uint32_t& r3, uint32_t addr) {
    asm volatile("ldmatrix.sync.aligned.m8n8.x4.shared.b16 {%0,%1,%2,%3}, [%4];"
                 : "=r"(r0), "=r"(r1), "=r"(r2), "=r"(r3) : "r"(addr));
}

__device__ __forceinline__ void mma16816(float* c, const uint32_t* a,
                                         const uint32_t* b) {
    asm volatile(
        "mma.sync.aligned.m16n8k16.row.col.f32.f16.f16.f32 "
        "{%0,%1,%2,%3}, {%4,%5,%6,%7}, {%8,%9}, {%0,%1,%2,%3};"
        : "+f"(c[0]), "+f"(c[1]), "+f"(c[2]), "+f"(c[3])
        : "r"(a[0]), "r"(a[1]), "r"(a[2]), "r"(a[3]), "r"(b[0]), "r"(b[1]));
}

// ======================= fused prep kernel =======================
static constexpr int XB = 8192;
static constexpr int WB = 4096;

__global__ void __launch_bounds__(256) prep_kernel(const float4* __restrict__ x,
                                                   const float4* __restrict__ w) {
    if (blockIdx.x < XB) {
        const int n4 = (int)((size_t)MDIM * KDIM / 4);
        uint2* o = reinterpret_cast<uint2*>(g_xh);
        int i = blockIdx.x * 256 + threadIdx.x;
        int st = XB * 256;
        for (; i < n4; i += st) {
            float4 v = x[i];
            __half2 a = __floats2half2_rn(v.x, v.y);
            __half2 b = __floats2half2_rn(v.z, v.w);
            union { __half2 h; uint32_t u; } pa, pb;
            pa.h = a; pb.h = b;
            o[i] = make_uint2(pa.u, pb.u);
        }
    } else {
        const int n4 = (int)((size_t)NDIM * KDIM / 4);
        uint2* o = reinterpret_cast<uint2*>(g_wb);
        int i = (blockIdx.x - XB) * 256 + threadIdx.x;
        int st = WB * 256;
        for (; i < n4; i += st) {
            float4 v = w[i];
            __half2 a = __floats2half2_rn(v.x >= 0.f ? 1.f : -1.f, v.y >= 0.f ? 1.f : -1.f);
            __half2 b = __floats2half2_rn(v.z >= 0.f ? 1.f : -1.f, v.w >= 0.f ? 1.f : -1.f);
            union { __half2 h; uint32_t u; } pa, pb;
            pa.h = a; pb.h = b;
            o[i] = make_uint2(pa.u, pb.u);
        }
    }
}

// ======================= GEMM kernel =============================
// 256 threads = 8 warps, warp layout 2 (M) x 4 (N), warp tile 64x32.
// 2 CTAs/SM. R9 structure (compact dynamic loop, warp-staggered ks,
// prefetch after first ks block) + XOR-only LDSM addressing + no %3.
__global__ void __launch_bounds__(256, 2) gemm_kernel(const float* __restrict__ bias,
                                                      float* __restrict__ out) {
    extern __shared__ char smem[];
    const uint32_t smem_base = smem_u32(smem);
    const int tid = threadIdx.x;
    const int wid = tid >> 5;
    const int lane = tid & 31;

    // grouped rasterization for L2 locality
    constexpr int NTN = NDIM / BN;  // 32
    constexpr int GM = 8;
    int pid = blockIdx.x;
    int group = pid / (GM * NTN);
    int rem = pid % (GM * NTN);
    int pm = group * GM + (rem % GM);
    int pn = rem / GM;
    const int m0 = pm * BM;
    const int n0 = pn * BN;

    if (tid < BN) reinterpret_cast<float*>(smem + SM_BIAS)[tid] = bias[n0 + tid];

    // ---- async stage loader ----
    auto load_stage = [&](uint32_t sA, int j) {
        uint32_t sB = sA + A_BYTES;
        const __half* gA = &g_xh[(size_t)m0 * KDIM + (size_t)j * BK];
        const __half* gB = &g_wb[(size_t)n0 * KDIM + (size_t)j * BK];
        #pragma unroll
        for (int i = 0; i < 4; i++) {
            int q = tid + i * 256;
            int r = q >> 3, c = q & 7;
            uint32_t so = (uint32_t)(r * 128 + ((c * 16) ^ ((r & 7) * 16)));
            cpasync16(sA + so, gA + (size_t)r * KDIM + c * 8);
        }
        #pragma unroll
        for (int i = 0; i < 4; i++) {
            int q = tid + i * 256;
            int r = q >> 3, c = q & 7;
            uint32_t so = (uint32_t)(r * 128 + ((c * 16) ^ ((r & 7) * 16)));
            cpasync16(sB + so, gB + (size_t)r * KDIM + c * 8);
        }
    };

    const uint32_t stg0 = smem_base + SM_STAGE0;
    const uint32_t stg2 = stg0 + 2 * STAGE_BYTES;

    load_stage(stg0, 0);
    asm volatile("cp.async.commit_group;");
    load_stage(stg0 + STAGE_BYTES, 1);
    asm volatile("cp.async.commit_group;");

    // ---- per-warp fragment addressing ----
    const int warpM = wid & 1;          // 0..1
    const int warpN = wid >> 1;         // 0..3
    const int l16 = lane & 15;
    const uint32_t colb = (uint32_t)((lane >> 4) * 16);

    // precomputed (rowOff + colb^xor); per-LDSM address = (stage+off) ^ (ks*32)
    uint32_t offA[4];                   // 4 m16 frags -> 64 rows
    #pragma unroll
    for (int mf = 0; mf < 4; mf++) {
        int row = warpM * 64 + mf * 16 + l16;
        offA[mf] = (uint32_t)(row * 128) + (colb ^ (uint32_t)((row & 7) * 16));
    }
    uint32_t offB[2];                   // 2 n16 groups -> 32 cols
    #pragma unroll
    for (int nh = 0; nh < 2; nh++) {
        int row = warpN * 32 + nh * 16 + l16;
        offB[nh] = (uint32_t)(row * 128) + (colb ^ (uint32_t)((row & 7) * 16));
    }

    float acc[4][4][4];
    #pragma unroll
    for (int mf = 0; mf < 4; mf++)
        #pragma unroll
        for (int nf = 0; nf < 4; nf++)
            #pragma unroll
            for (int k = 0; k < 4; k++) acc[mf][nf][k] = 0.f;

    const int ks0 = wid & 3;    // warp phase stagger

    // one ks block: 6 LDSM.x4 (XOR-addressed) + 16 HMMA
    auto compute_ks = [&](uint32_t sA, uint32_t sB, int ks) {
        const uint32_t kx = (uint32_t)(ks * 32);
        uint32_t a[4][4];
        ldsm_x4(a[0][0], a[0][1], a[0][2], a[0][3], (sA + offA[0]) ^ kx);
        ldsm_x4(a[1][0], a[1][1], a[1][2], a[1][3], (sA + offA[1]) ^ kx);
        ldsm_x4(a[2][0], a[2][1], a[2][2], a[2][3], (sA + offA[2]) ^ kx);
        ldsm_x4(a[3][0], a[3][1], a[3][2], a[3][3], (sA + offA[3]) ^ kx);
        uint32_t br[2][4];
        ldsm_x4(br[0][0], br[0][1], br[0][2], br[0][3], (sB + offB[0]) ^ kx);
        ldsm_x4(br[1][0], br[1][1], br[1][2], br[1][3], (sB + offB[1]) ^ kx);
        #pragma unroll
        for (int mf = 0; mf < 4; mf++) {
            #pragma unroll
            for (int nf = 0; nf < 4; nf++) {
                uint32_t b2[2];
                b2[0] = br[nf >> 1][nf & 1];
                b2[1] = br[nf >> 1][(nf & 1) + 2];
                mma16816(acc[mf][nf], a[mf], b2);
            }
        }
    };

    // ---- main loop (compact body; stage pointers advance by add+wrap) ----
    uint32_t sCur = stg0;                       // stage for iter it
    uint32_t sPre = stg2;                       // stage for iter it+2
    for (int it = 0; it < NIT; ++it) {
        asm volatile("cp.async.wait_group %0;" :: "n"(NSTAGE - 2));
        __syncthreads();

        const uint32_t sA = sCur, sB = sCur + A_BYTES;

        // first ks block (staggered per warp) before issuing prefetch
        compute_ks(sA, sB, ks0);

        int j = it + NSTAGE - 1;
        if (j < NIT) load_stage(sPre, j);
        asm volatile("cp.async.commit_group;");

        #pragma unroll
        for (int kk = 1; kk < 4; kk++)
            compute_ks(sA, sB, (ks0 + kk) & 3);

        sCur = (sCur == stg2) ? stg0 : sCur + STAGE_BYTES;
        sPre = (sPre == stg2) ? stg0 : sPre + STAGE_BYTES;
    }

    // ---- epilogue ----
    const float* sb = reinterpret_cast<const float*>(smem + SM_BIAS);
    const int groupid = lane >> 2;
    const int tid4 = lane & 3;
    #pragma unroll
    for (int mf = 0; mf < 4; mf++) {
        int m = m0 + warpM * 64 + mf * 16 + groupid;
        #pragma unroll
        for (int nf = 0; nf < 4; nf++) {
            int nl = warpN * 32 + nf * 8 + tid4 * 2;
            int n = n0 + nl;
            float2 v0;
            v0.x = acc[mf][nf][0] + sb[nl];
            v0.y = acc[mf][nf][1] + sb[nl + 1];
            *reinterpret_cast<float2*>(out + (size_t)m * NDIM + n) = v0;
            float2 v1;
            v1.x = acc[mf][nf][2] + sb[nl];
            v1.y = acc[mf][nf][3] + sb[nl + 1];
            *reinterpret_cast<float2*>(out + (size_t)(m + 8) * NDIM + n) = v1;
        }
    }
}

// ======================= launch ==================================
extern "C" void kernel_launch(void* const* d_in, const int* in_sizes, int n_in,
                              void* d_out, int out_size) {
    (void)in_sizes; (void)n_in; (void)out_size;
    const float* x    = (const float*)d_in[0];
    const float* w    = (const float*)d_in[1];
    const float* bias = (const float*)d_in[2];
    float* out = (float*)d_out;

    prep_kernel<<<XB + WB, 256>>>((const float4*)x, (const float4*)w);

    cudaFuncSetAttribute(gemm_kernel, cudaFuncAttributeMaxDynamicSharedMemorySize,
                         (int)SMEM_TOTAL);
    int grid = (MDIM / BM) * (NDIM / BN);  // 4096
    gemm_kernel<<<grid, 256, SMEM_TOTAL>>>(bias, out);
}

// round 14
// speedup vs baseline: 1.7948x; 1.7948x over previous
#include <cuda_runtime.h>
#include <cuda_fp16.h>
#include <cstdint>

// ======================= problem constants =======================
static constexpr int MDIM = 16384;   // 8*2048
static constexpr int NDIM = 4096;
static constexpr int KDIM = 4096;

static constexpr int BM = 128;
static constexpr int BN = 128;
static constexpr int BK = 64;            // 64 fp16 = 128B per row
static constexpr int NSTAGE = 3;
static constexpr int NIT = KDIM / BK;    // 64

static constexpr int A_BYTES = BM * BK * 2;            // 16384
static constexpr int B_BYTES = BN * BK * 2;            // 16384
static constexpr int STAGE_BYTES = A_BYTES + B_BYTES;  // 32768

static constexpr uint32_t SM_BIAS   = 0;     // 128 floats
static constexpr uint32_t SM_STAGE0 = 1024;
static constexpr uint32_t SMEM_TOTAL = SM_STAGE0 + NSTAGE * STAGE_BYTES; // 99328

// ======================= scratch (static device globals) =========
__device__ __align__(256) __half g_xh[(size_t)MDIM * KDIM];  // 128 MB
__device__ __align__(256) __half g_wb[(size_t)NDIM * KDIM];  //  32 MB

// ======================= helpers =================================
__device__ __forceinline__ uint32_t smem_u32(const void* p) {
    uint32_t a;
    asm("{ .reg .u64 t; cvta.to.shared.u64 t, %1; cvt.u32.u64 %0, t; }"
        : "=r"(a) : "l"(p));
    return a;
}

__device__ __forceinline__ void cpasync16(uint32_t saddr, const void* g) {
    asm volatile("cp.async.cg.shared.global [%0], [%1], 16;" :: "r"(saddr), "l"(g));
}

__device__ __forceinline__ void ldsm_x4(uint32_t& r0, uint32_t& r1,
                                        uint32_t& r2, uint32_t& r3, uint32_t addr) {
    asm volatile("ldmatrix.sync.aligned.m8n8.x4.shared.b16 {%0,%1,%2,%3}, [%4];"
                 : "=r"(r0), "=r"(r1), "=r"(r2), "=r"(r3) : "r"(addr));
}

__device__ __forceinline__ void mma16816(float* c, const uint32_t* a,
                                         const uint32_t* b) {
    asm volatile(
        "mma.sync.aligned.m16n8k16.row.col.f32.f16.f16.f32 "
        "{%0,%1,%2,%3}, {%4,%5,%6,%7}, {%8,%9}, {%0,%1,%2,%3};"
        : "+f"(c[0]), "+f"(c[1]), "+f"(c[2]), "+f"(c[3])
        : "r"(a[0]), "r"(a[1]), "r"(a[2]), "r"(a[3]), "r"(b[0]), "r"(b[1]));
}

// ======================= fused prep kernel =======================
static constexpr int XB = 8192;
static constexpr int WB = 4096;

__global__ void __launch_bounds__(256) prep_kernel(const float4* __restrict__ x,
                                                   const float4* __restrict__ w) {
    if (blockIdx.x < XB) {
        const int n4 = (int)((size_t)MDIM * KDIM / 4);
        uint2* o = reinterpret_cast<uint2*>(g_xh);
        int i = blockIdx.x * 256 + threadIdx.x;
        int st = XB * 256;
        for (; i < n4; i += st) {
            float4 v = x[i];
            __half2 a = __floats2half2_rn(v.x, v.y);
            __half2 b = __floats2half2_rn(v.z, v.w);
            union { __half2 h; uint32_t u; } pa, pb;
            pa.h = a; pb.h = b;
            o[i] = make_uint2(pa.u, pb.u);
        }
    } else {
        const int n4 = (int)((size_t)NDIM * KDIM / 4);
        uint2* o = reinterpret_cast<uint2*>(g_wb);
        int i = (blockIdx.x - XB) * 256 + threadIdx.x;
        int st = WB * 256;
        for (; i < n4; i += st) {
            float4 v = w[i];
            __half2 a = __floats2half2_rn(v.x >= 0.f ? 1.f : -1.f, v.y >= 0.f ? 1.f : -1.f);
            __half2 b = __floats2half2_rn(v.z >= 0.f ? 1.f : -1.f, v.w >= 0.f ? 1.f : -1.f);
            union { __half2 h; uint32_t u; } pa, pb;
            pa.h = a; pb.h = b;
            o[i] = make_uint2(pa.u, pb.u);
        }
    }
}

// ======================= GEMM kernel =============================
// 256 threads = 8 warps, warp layout 2 (M) x 4 (N), warp tile 64x32.
// 2 CTAs/SM. Exact R9 structure; ONLY change: loader addresses hoisted
// out of the loop (so_i = so_0 + 4096*i, g_i = g_0 + 32*i*KDIM, k-advance
// by pointer bump).
__global__ void __launch_bounds__(256, 2) gemm_kernel(const float* __restrict__ bias,
                                                      float* __restrict__ out) {
    extern __shared__ char smem[];
    const uint32_t smem_base = smem_u32(smem);
    const int tid = threadIdx.x;
    const int wid = tid >> 5;
    const int lane = tid & 31;

    // grouped rasterization for L2 locality
    constexpr int NTN = NDIM / BN;  // 32
    constexpr int GM = 8;
    int pid = blockIdx.x;
    int group = pid / (GM * NTN);
    int rem = pid % (GM * NTN);
    int pm = group * GM + (rem % GM);
    int pn = rem / GM;
    const int m0 = pm * BM;
    const int n0 = pn * BN;

    if (tid < BN) reinterpret_cast<float*>(smem + SM_BIAS)[tid] = bias[n0 + tid];

    // ---- hoisted loader addressing ----
    // thread covers rows r0 + 32*i (i=0..3), col chunk c (16B); low-3 bits of
    // row are constant across i, so the swizzle term is too.
    const int r0 = tid >> 3;
    const int c  = tid & 7;
    const uint32_t so0 = (uint32_t)(r0 * 128 + ((c * 16) ^ ((r0 & 7) * 16)));
    const __half* gA = &g_xh[(size_t)(m0 + r0) * KDIM + c * 8];
    const __half* gB = &g_wb[(size_t)(n0 + r0) * KDIM + c * 8];

    // load one stage at smem base sA from current gA/gB (k-offset baked into ptrs)
    auto load_stage = [&](uint32_t sA, const __half* pA, const __half* pB) {
        uint32_t sB = sA + A_BYTES;
        #pragma unroll
        for (int i = 0; i < 4; i++)
            cpasync16(sA + so0 + (uint32_t)(i * 4096), pA + (size_t)(32 * i) * KDIM);
        #pragma unroll
        for (int i = 0; i < 4; i++)
            cpasync16(sB + so0 + (uint32_t)(i * 4096), pB + (size_t)(32 * i) * KDIM);
    };

    load_stage(smem_base + SM_STAGE0, gA, gB);
    asm volatile("cp.async.commit_group;");
    load_stage(smem_base + SM_STAGE0 + STAGE_BYTES, gA + BK, gB + BK);
    asm volatile("cp.async.commit_group;");
    const __half* gAp = gA + 2 * BK;   // prefetch pointers (k-chunk it+2)
    const __half* gBp = gB + 2 * BK;

    // ---- per-warp fragment addressing (exact R9) ----
    const int warpM = wid & 1;          // 0..1
    const int warpN = wid >> 1;         // 0..3
    const int l16 = lane & 15;
    const uint32_t colb = (uint32_t)((lane >> 4) * 16);

    uint32_t rowOffA[4], xorA[4];       // 4 m16 frags -> 64 rows
    #pragma unroll
    for (int mf = 0; mf < 4; mf++) {
        int row = warpM * 64 + mf * 16 + l16;
        rowOffA[mf] = (uint32_t)(row * 128);
        xorA[mf] = (uint32_t)((row & 7) * 16);
    }
    uint32_t rowOffB[2], xorB[2];       // 2 n16 groups -> 32 cols
    #pragma unroll
    for (int nh = 0; nh < 2; nh++) {
        int row = warpN * 32 + nh * 16 + l16;
        rowOffB[nh] = (uint32_t)(row * 128);
        xorB[nh] = (uint32_t)((row & 7) * 16);
    }

    float acc[4][4][4];
    #pragma unroll
    for (int mf = 0; mf < 4; mf++)
        #pragma unroll
        for (int nf = 0; nf < 4; nf++)
            #pragma unroll
            for (int k = 0; k < 4; k++) acc[mf][nf][k] = 0.f;

    // one ks block: 6 LDSM.x4 + 16 HMMA (exact R9)
    auto compute_ks = [&](uint32_t sA, uint32_t sB, int ks) {
        const uint32_t kcol = (uint32_t)(ks * 32) + colb;
        uint32_t a[4][4];
        #pragma unroll
        for (int mf = 0; mf < 4; mf++)
            ldsm_x4(a[mf][0], a[mf][1], a[mf][2], a[mf][3],
                    sA + rowOffA[mf] + (kcol ^ xorA[mf]));
        uint32_t br[2][4];
        #pragma unroll
        for (int nh = 0; nh < 2; nh++)
            ldsm_x4(br[nh][0], br[nh][1], br[nh][2], br[nh][3],
                    sB + rowOffB[nh] + (kcol ^ xorB[nh]));
        #pragma unroll
        for (int mf = 0; mf < 4; mf++) {
            #pragma unroll
            for (int nf = 0; nf < 4; nf++) {
                uint32_t b2[2];
                b2[0] = br[nf >> 1][nf & 1];
                b2[1] = br[nf >> 1][(nf & 1) + 2];
                mma16816(acc[mf][nf], a[mf], b2);
            }
        }
    };

    // ---- main loop (exact R9) ----
    const int ks0 = wid & 3;    // warp-dependent phase
    for (int it = 0; it < NIT; ++it) {
        asm volatile("cp.async.wait_group %0;" :: "n"(NSTAGE - 2));
        __syncthreads();

        int cur = it % NSTAGE;
        uint32_t sA = smem_base + SM_STAGE0 + (uint32_t)cur * STAGE_BYTES;
        uint32_t sB = sA + A_BYTES;

        // first ks block (staggered per warp) before issuing prefetch
        compute_ks(sA, sB, ks0);

        int j = it + NSTAGE - 1;
        if (j < NIT) {
            uint32_t sPre = smem_base + SM_STAGE0 + (uint32_t)(j % NSTAGE) * STAGE_BYTES;
            load_stage(sPre, gAp, gBp);
        }
        asm volatile("cp.async.commit_group;");
        gAp += BK;
        gBp += BK;

        #pragma unroll
        for (int kk = 1; kk < 4; kk++)
            compute_ks(sA, sB, (ks0 + kk) & 3);
    }

    // ---- epilogue (exact R9) ----
    const float* sb = reinterpret_cast<const float*>(smem + SM_BIAS);
    const int groupid = lane >> 2;
    const int tid4 = lane & 3;
    #pragma unroll
    for (int mf = 0; mf < 4; mf++) {
        int m = m0 + warpM * 64 + mf * 16 + groupid;
        #pragma unroll
        for (int nf = 0; nf < 4; nf++) {
            int nl = warpN * 32 + nf * 8 + tid4 * 2;
            int n = n0 + nl;
            float2 v0;
            v0.x = acc[mf][nf][0] + sb[nl];
            v0.y = acc[mf][nf][1] + sb[nl + 1];
            *reinterpret_cast<float2*>(out + (size_t)m * NDIM + n) = v0;
            float2 v1;
            v1.x = acc[mf][nf][2] + sb[nl];
            v1.y = acc[mf][nf][3] + sb[nl + 1];
            *reinterpret_cast<float2*>(out + (size_t)(m + 8) * NDIM + n) = v1;
        }
    }
}

// ======================= launch ==================================
extern "C" void kernel_launch(void* const* d_in, const int* in_sizes, int n_in,
                              void* d_out, int out_size) {
    (void)in_sizes; (void)n_in; (void)out_size;
    const float* x    = (const float*)d_in[0];
    const float* w    = (const float*)d_in[1];
    const float* bias = (const float*)d_in[2];
    float* out = (float*)d_out;

    prep_kernel<<<XB + WB, 256>>>((const float4*)x, (const float4*)w);

    cudaFuncSetAttribute(gemm_kernel, cudaFuncAttributeMaxDynamicSharedMemorySize,
                         (int)SMEM_TOTAL);
    int grid = (MDIM / BM) * (NDIM / BN);  // 4096
    gemm_kernel<<<grid, 256, SMEM_TOTAL>>>(bias, out);
}

// round 16
// speedup vs baseline: 1.9099x; 1.0641x over previous
#include <cuda_runtime.h>
#include <cuda_fp16.h>
#include <cstdint>

// ======================= problem constants =======================
static constexpr int MDIM = 16384;   // 8*2048
static constexpr int NDIM = 4096;
static constexpr int KDIM = 4096;

static constexpr int BM = 128;
static constexpr int BN = 128;
static constexpr int BK = 64;            // 64 fp16 = 128B per row
static constexpr int NSTAGE = 3;
static constexpr int NIT = KDIM / BK;    // 64
static constexpr int KC = KDIM / BK;     // 64 k-chunks per tile row

static constexpr int A_BYTES = BM * BK * 2;            // 16384 (one block)
static constexpr int B_BYTES = BN * BK * 2;            // 16384
static constexpr int STAGE_BYTES = A_BYTES + B_BYTES;  // 32768

static constexpr uint32_t SM_BIAS   = 0;     // 128 floats = 512B
static constexpr uint32_t SM_MBAR   = 512;   // 3 mbarriers (8B each)
static constexpr uint32_t SM_STAGE0 = 1024;
static constexpr uint32_t SMEM_TOTAL = SM_STAGE0 + NSTAGE * STAGE_BYTES; // 99328

// ======================= scratch (static device globals) =========
// Pre-swizzled tile-contiguous layout: block (tile, kc) is 16 KB contiguous,
// holding rows r=0..127 x 8 chunks of 16B with chunk position sc = c ^ (r&7).
__device__ __align__(256) __half g_xh[(size_t)MDIM * KDIM];  // 128 MB
__device__ __align__(256) __half g_wb[(size_t)NDIM * KDIM];  //  32 MB

// ======================= PTX helpers =============================
__device__ __forceinline__ uint32_t smem_u32(const void* p) {
    uint32_t a;
    asm("{ .reg .u64 t; cvta.to.shared.u64 t, %1; cvt.u32.u64 %0, t; }"
        : "=r"(a) : "l"(p));
    return a;
}

#define MBARRIER_INIT(addr, cnt) \
    asm volatile("mbarrier.init.shared.b64 [%0], %1;" \
                 :: "r"((uint32_t)(addr)), "r"((uint32_t)(cnt)) : "memory")

#define MBARRIER_EXPECT_TX(addr, bytes) \
    asm volatile("mbarrier.arrive.expect_tx.shared.b64 _, [%0], %1;" \
                 :: "r"((uint32_t)(addr)), "r"((uint32_t)(bytes)) : "memory")

#define MBARRIER_WAIT_PARITY(mbar_smem_addr, phase_parity) do { \
    uint32_t _mbar = (uint32_t)(mbar_smem_addr); \
    uint32_t _parity = (uint32_t)(phase_parity); \
    uint32_t _done; \
    asm volatile( \
        "{\n\t" \
        ".reg .pred p;\n\t" \
        "mbarrier.try_wait.parity.acquire.cta.shared::cta.b64 p, [%1], %2;\n\t" \
        "selp.b32 %0, 1, 0, p;\n\t" \
        "}" \
        : "=r"(_done) : "r"(_mbar), "r"(_parity) : "memory"); \
    if (!_done) { \
        asm volatile( \
            "{\n\t" \
            ".reg .pred P1;\n\t" \
            "WAIT_LOOP_%=:\n\t" \
            "mbarrier.try_wait.parity.acquire.cta.shared::cta.b64 P1, [%0], %1, 0x989680;\n\t" \
            "@P1 bra.uni WAIT_DONE_%=;\n\t" \
            "bra.uni WAIT_LOOP_%=;\n\t" \
            "WAIT_DONE_%=:\n\t" \
            "}" \
            :: "r"(_mbar), "r"(_parity) : "memory"); \
    } \
} while (0)

__device__ __forceinline__ void bulk_g2s(uint32_t dst_smem, const void* src,
                                         uint32_t bytes, uint32_t mbar) {
    asm volatile(
        "cp.async.bulk.shared::cluster.global.mbarrier::complete_tx::bytes "
        "[%0], [%1], %2, [%3];"
        :: "r"(dst_smem), "l"(src), "r"(bytes), "r"(mbar) : "memory");
}

__device__ __forceinline__ void ldsm_x4(uint32_t& r0, uint32_t& r1,
                                        uint32_t& r2, uint32_t& r3, uint32_t addr) {
    asm volatile("ldmatrix.sync.aligned.m8n8.x4.shared.b16 {%0,%1,%2,%3}, [%4];"
                 : "=r"(r0), "=r"(r1), "=r"(r2), "=r"(r3) : "r"(addr));
}

__device__ __forceinline__ void mma16816(float* c, const uint32_t* a,
                                         const uint32_t* b) {
    asm volatile(
        "mma.sync.aligned.m16n8k16.row.col.f32.f16.f16.f32 "
        "{%0,%1,%2,%3}, {%4,%5,%6,%7}, {%8,%9}, {%0,%1,%2,%3};"
        : "+f"(c[0]), "+f"(c[1]), "+f"(c[2]), "+f"(c[3])
        : "r"(a[0]), "r"(a[1]), "r"(a[2]), "r"(a[3]), "r"(b[0]), "r"(b[1]));
}

// ======================= fused prep kernel =======================
// Writes the pre-swizzled tile-contiguous layout. Output-linear iteration:
// chunk i (16B) -> block b = i/1024, w = i%1024, row r = w/8, slot sc = w%8,
// source col-chunk cc = sc ^ (r&7).
static constexpr int XB = 8192;
static constexpr int WB = 4096;

__global__ void __launch_bounds__(256) prep_kernel(const float4* __restrict__ x,
                                                   const float4* __restrict__ w) {
    if (blockIdx.x < XB) {
        const int nchunk = (int)((size_t)MDIM * KDIM / 8);   // 16B chunks
        uint4* o = reinterpret_cast<uint4*>(g_xh);
        int i = blockIdx.x * 256 + threadIdx.x;
        const int st = XB * 256;
        for (; i < nchunk; i += st) {
            int b = i >> 10;
            int wdx = i & 1023;
            int r = wdx >> 3, sc = wdx & 7;
            int cc = sc ^ (r & 7);
            int m = ((b >> 6) << 7) + r;          // tile*128 + r
            int kc = b & 63;
            size_t e4 = ((size_t)m * KDIM + (kc << 6) + (cc << 3)) >> 2;
            float4 v0 = x[e4];
            float4 v1 = x[e4 + 1];
            union { __half2 h; uint32_t u; } p0, p1, p2, p3;
            p0.h = __floats2half2_rn(v0.x, v0.y);
            p1.h = __floats2half2_rn(v0.z, v0.w);
            p2.h = __floats2half2_rn(v1.x, v1.y);
            p3.h = __floats2half2_rn(v1.z, v1.w);
            o[i] = make_uint4(p0.u, p1.u, p2.u, p3.u);
        }
    } else {
        const int nchunk = (int)((size_t)NDIM * KDIM / 8);
        uint4* o = reinterpret_cast<uint4*>(g_wb);
        int i = (blockIdx.x - XB) * 256 + threadIdx.x;
        const int st = WB * 256;
        for (; i < nchunk; i += st) {
            int b = i >> 10;
            int wdx = i & 1023;
            int r = wdx >> 3, sc = wdx & 7;
            int cc = sc ^ (r & 7);
            int n = ((b >> 6) << 7) + r;
            int kc = b & 63;
            size_t e4 = ((size_t)n * KDIM + (kc << 6) + (cc << 3)) >> 2;
            float4 v0 = w[e4];
            float4 v1 = w[e4 + 1];
            union { __half2 h; uint32_t u; } p0, p1, p2, p3;
            p0.h = __floats2half2_rn(v0.x >= 0.f ? 1.f : -1.f, v0.y >= 0.f ? 1.f : -1.f);
            p1.h = __floats2half2_rn(v0.z >= 0.f ? 1.f : -1.f, v0.w >= 0.f ? 1.f : -1.f);
            p2.h = __floats2half2_rn(v1.x >= 0.f ? 1.f : -1.f, v1.y >= 0.f ? 1.f : -1.f);
            p3.h = __floats2half2_rn(v1.z >= 0.f ? 1.f : -1.f, v1.w >= 0.f ? 1.f : -1.f);
            o[i] = make_uint4(p0.u, p1.u, p2.u, p3.u);
        }
    }
}

// ======================= GEMM kernel =============================
// 256 threads = 8 warps, warp layout 2 (M) x 4 (N), warp tile 64x32.
// 2 CTAs/SM. Compute core identical to R14; loader replaced by
// cp.async.bulk (elected thread) + mbarrier full[3].
__global__ void __launch_bounds__(256, 2) gemm_kernel(const float* __restrict__ bias,
                                                      float* __restrict__ out) {
    extern __shared__ char smem[];
    const uint32_t smem_base = smem_u32(smem);
    const int tid = threadIdx.x;
    const int wid = tid >> 5;
    const int lane = tid & 31;

    // grouped rasterization for L2 locality
    constexpr int NTN = NDIM / BN;  // 32
    constexpr int GM = 8;
    int pid = blockIdx.x;
    int group = pid / (GM * NTN);
    int rem = pid % (GM * NTN);
    int pm = group * GM + (rem % GM);
    int pn = rem / GM;
    const int m0 = pm * BM;
    const int n0 = pn * BN;

    if (tid < BN) reinterpret_cast<float*>(smem + SM_BIAS)[tid] = bias[n0 + tid];

    // block sources: block (tile, kc) at byte offset (tile*KC + kc)*16384
    const char* srcA = reinterpret_cast<const char*>(g_xh) + (size_t)pm * KC * A_BYTES;
    const char* srcB = reinterpret_cast<const char*>(g_wb) + (size_t)pn * KC * B_BYTES;

    if (tid == 0) {
        #pragma unroll
        for (int s = 0; s < NSTAGE; s++) MBARRIER_INIT(smem_base + SM_MBAR + 8 * s, 1);
    }
    __syncthreads();

    // prologue: arm stages 0,1 with k-chunks 0,1
    if (tid == 0) {
        #pragma unroll
        for (int j = 0; j < NSTAGE - 1; j++) {
            uint32_t mb = smem_base + SM_MBAR + 8 * j;
            uint32_t dst = smem_base + SM_STAGE0 + (uint32_t)j * STAGE_BYTES;
            MBARRIER_EXPECT_TX(mb, STAGE_BYTES);
            bulk_g2s(dst, srcA + (size_t)j * A_BYTES, A_BYTES, mb);
            bulk_g2s(dst + A_BYTES, srcB + (size_t)j * B_BYTES, B_BYTES, mb);
        }
    }

    // ---- per-warp fragment addressing (exact R14) ----
    const int warpM = wid & 1;          // 0..1
    const int warpN = wid >> 1;         // 0..3
    const int l16 = lane & 15;
    const uint32_t colb = (uint32_t)((lane >> 4) * 16);

    uint32_t rowOffA[4], xorA[4];       // 4 m16 frags -> 64 rows
    #pragma unroll
    for (int mf = 0; mf < 4; mf++) {
        int row = warpM * 64 + mf * 16 + l16;
        rowOffA[mf] = (uint32_t)(row * 128);
        xorA[mf] = (uint32_t)((row & 7) * 16);
    }
    uint32_t rowOffB[2], xorB[2];       // 2 n16 groups -> 32 cols
    #pragma unroll
    for (int nh = 0; nh < 2; nh++) {
        int row = warpN * 32 + nh * 16 + l16;
        rowOffB[nh] = (uint32_t)(row * 128);
        xorB[nh] = (uint32_t)((row & 7) * 16);
    }

    float acc[4][4][4];
    #pragma unroll
    for (int mf = 0; mf < 4; mf++)
        #pragma unroll
        for (int nf = 0; nf < 4; nf++)
            #pragma unroll
            for (int k = 0; k < 4; k++) acc[mf][nf][k] = 0.f;

    // one ks block: 6 LDSM.x4 + 16 HMMA (exact R14)
    auto compute_ks = [&](uint32_t sA, uint32_t sB, int ks) {
        const uint32_t kcol = (uint32_t)(ks * 32) + colb;
        uint32_t a[4][4];
        #pragma unroll
        for (int mf = 0; mf < 4; mf++)
            ldsm_x4(a[mf][0], a[mf][1], a[mf][2], a[mf][3],
                    sA + rowOffA[mf] + (kcol ^ xorA[mf]));
        uint32_t br[2][4];
        #pragma unroll
        for (int nh = 0; nh < 2; nh++)
            ldsm_x4(br[nh][0], br[nh][1], br[nh][2], br[nh][3],
                    sB + rowOffB[nh] + (kcol ^ xorB[nh]));
        #pragma unroll
        for (int mf = 0; mf < 4; mf++) {
            #pragma unroll
            for (int nf = 0; nf < 4; nf++) {
                uint32_t b2[2];
                b2[0] = br[nf >> 1][nf & 1];
                b2[1] = br[nf >> 1][(nf & 1) + 2];
                mma16816(acc[mf][nf], a[mf], b2);
            }
        }
    };

    // ---- main loop ----
    const int ks0 = wid & 3;    // warp-dependent phase
    for (int it = 0; it < NIT; ++it) {
        // all warps finished reading stage (it-1)%3 == (it+2)%3 in iter it-1
        __syncthreads();

        int j = it + NSTAGE - 1;
        if (tid == 0 && j < NIT) {
            int s = j % NSTAGE;
            uint32_t mb = smem_base + SM_MBAR + 8 * s;
            uint32_t dst = smem_base + SM_STAGE0 + (uint32_t)s * STAGE_BYTES;
            MBARRIER_EXPECT_TX(mb, STAGE_BYTES);
            bulk_g2s(dst, srcA + (size_t)j * A_BYTES, A_BYTES, mb);
            bulk_g2s(dst + A_BYTES, srcB + (size_t)j * B_BYTES, B_BYTES, mb);
        }

        int cur = it % NSTAGE;
        MBARRIER_WAIT_PARITY(smem_base + SM_MBAR + 8 * cur, (uint32_t)((it / 3) & 1));

        uint32_t sA = smem_base + SM_STAGE0 + (uint32_t)cur * STAGE_BYTES;
        uint32_t sB = sA + A_BYTES;

        compute_ks(sA, sB, ks0);
        #pragma unroll
        for (int kk = 1; kk < 4; kk++)
            compute_ks(sA, sB, (ks0 + kk) & 3);
    }

    // ---- epilogue (exact R14) ----
    const float* sb = reinterpret_cast<const float*>(smem + SM_BIAS);
    const int groupid = lane >> 2;
    const int tid4 = lane & 3;
    #pragma unroll
    for (int mf = 0; mf < 4; mf++) {
        int m = m0 + warpM * 64 + mf * 16 + groupid;
        #pragma unroll
        for (int nf = 0; nf < 4; nf++) {
            int nl = warpN * 32 + nf * 8 + tid4 * 2;
            int n = n0 + nl;
            float2 v0;
            v0.x = acc[mf][nf][0] + sb[nl];
            v0.y = acc[mf][nf][1] + sb[nl + 1];
            *reinterpret_cast<float2*>(out + (size_t)m * NDIM + n) = v0;
            float2 v1;
            v1.x = acc[mf][nf][2] + sb[nl];
            v1.y = acc[mf][nf][3] + sb[nl + 1];
            *reinterpret_cast<float2*>(out + (size_t)(m + 8) * NDIM + n) = v1;
        }
    }
}

// ======================= launch ==================================
extern "C" void kernel_launch(void* const* d_in, const int* in_sizes, int n_in,
                              void* d_out, int out_size) {
    (void)in_sizes; (void)n_in; (void)out_size;
    const float* x    = (const float*)d_in[0];
    const float* w    = (const float*)d_in[1];
    const float* bias = (const float*)d_in[2];
    float* out = (float*)d_out;

    prep_kernel<<<XB + WB, 256>>>((const float4*)x, (const float4*)w);

    cudaFuncSetAttribute(gemm_kernel, cudaFuncAttributeMaxDynamicSharedMemorySize,
                         (int)SMEM_TOTAL);
    int grid = (MDIM / BM) * (NDIM / BN);  // 4096
    gemm_kernel<<<grid, 256, SMEM_TOTAL>>>(bias, out);
}